// round 2
// baseline (speedup 1.0000x reference)
#include <cuda_runtime.h>
#include <cuda_bf16.h>

// Problem constants (fixed shapes for this problem instance)
#define NNODES 10000
#define BT 4            // B*T
#define FDIM 128
#define ROW (BT*FDIM)   // 512 floats per node row
#define EMAX 262144
#define MROWS (NNODES*BT)   // 40000 GEMM rows

// ---------------- device scratch (no allocation allowed) ----------------
__device__ float g_hA[NNODES*ROW];
__device__ float g_hB[NNODES*ROW];
__device__ float g_agg[NNODES*ROW];
__device__ int   g_deg[NNODES];
__device__ int   g_cursor[NNODES];
__device__ int   g_off[NNODES+1];
__device__ float g_invdeg[NNODES];
__device__ int   g_esrc_sorted[EMAX];

// ---------------- f32x2 packed math helpers ----------------
__device__ __forceinline__ unsigned long long pack2(float x) {
    unsigned long long r;
    asm("mov.b64 %0, {%1, %1};" : "=l"(r) : "f"(x));
    return r;
}
__device__ __forceinline__ void ffma2(unsigned long long& d,
                                      unsigned long long a,
                                      unsigned long long b) {
    asm("fma.rn.f32x2 %0, %1, %2, %0;" : "+l"(d) : "l"(a), "l"(b));
}
__device__ __forceinline__ float lo32(unsigned long long v) {
    return __uint_as_float((unsigned)(v & 0xffffffffull));
}
__device__ __forceinline__ float hi32(unsigned long long v) {
    return __uint_as_float((unsigned)(v >> 32));
}

// ---------------- setup kernels ----------------
__global__ void init_kernel() {
    int i = blockIdx.x * blockDim.x + threadIdx.x;
    if (i < NNODES) { g_deg[i] = 0; g_cursor[i] = 0; }
}

// feature [B,T,N,F] -> g_hA [N, BT, F]
__global__ void transpose_in_kernel(const float* __restrict__ feat) {
    int j = blockIdx.x * blockDim.x + threadIdx.x;   // float4 index over output
    const int TOT = NNODES * ROW / 4;                // 1,280,000
    if (j >= TOT) return;
    int n   = j >> 7;           // / 128   (BT * F/4 = 128 float4 per node)
    int rem = j & 127;
    int bt  = rem >> 5;         // / 32
    int f4  = rem & 31;
    float4 v = ((const float4*)feat)[(bt * NNODES + n) * 32 + f4];
    ((float4*)g_hA)[j] = v;
}

__global__ void degree_kernel(const int* __restrict__ edst, int E) {
    int e = blockIdx.x * blockDim.x + threadIdx.x;
    if (e < E) atomicAdd(&g_deg[edst[e]], 1);
}

// single-CTA blocked exclusive scan of deg -> off, plus inv_deg
__global__ void scan_kernel(int E) {
    __shared__ int buf[1024];
    __shared__ int carry_s;
    int tid = threadIdx.x;
    if (tid == 0) carry_s = 0;
    __syncthreads();
    for (int base = 0; base < NNODES; base += 1024) {
        int idx = base + tid;
        int v = (idx < NNODES) ? g_deg[idx] : 0;
        buf[tid] = v;
        __syncthreads();
        for (int off = 1; off < 1024; off <<= 1) {
            int t = (tid >= off) ? buf[tid - off] : 0;
            __syncthreads();
            buf[tid] += t;
            __syncthreads();
        }
        int excl = buf[tid] - v;
        int carry = carry_s;
        if (idx < NNODES) {
            g_off[idx] = carry + excl;
            g_invdeg[idx] = (v > 0) ? (1.0f / (float)v) : 0.0f;
        }
        __syncthreads();
        if (tid == 1023) carry_s = carry + buf[1023];
        __syncthreads();
    }
    if (tid == 0) g_off[NNODES] = E;
}

__global__ void bucket_kernel(const int* __restrict__ esrc,
                              const int* __restrict__ edst, int E) {
    int e = blockIdx.x * blockDim.x + threadIdx.x;
    if (e < E) {
        int d = edst[e];
        int p = g_off[d] + atomicAdd(&g_cursor[d], 1);
        g_esrc_sorted[p] = esrc[e];
    }
}

// ---------------- mean aggregation: one CTA per dst node ----------------
// src_sel: 0 -> read g_hA, 1 -> read g_hB   (resolved in DEVICE code)
__global__ void __launch_bounds__(128) agg_kernel(int src_sel) {
    const float* hin = (src_sel == 0) ? g_hA : g_hB;
    int n = blockIdx.x;
    int t = threadIdx.x;                  // 0..127, one float4 of the 512-float row
    int s = g_off[n];
    int e = g_off[n + 1];
    const float4* hv = (const float4*)hin;
    float4 a0 = make_float4(0.f, 0.f, 0.f, 0.f);
    float4 a1 = make_float4(0.f, 0.f, 0.f, 0.f);
    int i = s;
    for (; i + 1 < e; i += 2) {
        int s0 = g_esrc_sorted[i];
        int s1 = g_esrc_sorted[i + 1];
        float4 v0 = hv[s0 * 128 + t];
        float4 v1 = hv[s1 * 128 + t];
        a0.x += v0.x; a0.y += v0.y; a0.z += v0.z; a0.w += v0.w;
        a1.x += v1.x; a1.y += v1.y; a1.z += v1.z; a1.w += v1.w;
    }
    if (i < e) {
        int s0 = g_esrc_sorted[i];
        float4 v0 = hv[s0 * 128 + t];
        a0.x += v0.x; a0.y += v0.y; a0.z += v0.z; a0.w += v0.w;
    }
    float inv = g_invdeg[n];
    float4 r;
    r.x = (a0.x + a1.x) * inv;
    r.y = (a0.y + a1.y) * inv;
    r.z = (a0.z + a1.z) * inv;
    r.w = (a0.w + a1.w) * inv;
    ((float4*)g_agg)[n * 128 + t] = r;
}

// ---------------- fused GEMM: out = X0*Wself + X1*Wneigh + b ----------------
// M = 40000 rows, K = 256 (concat of h and h_neigh), N = 128 cols.
// 128x128 tile per CTA, 256 threads, 8x8 per thread, f32x2 packed FFMA.
// x_sel: 0 -> X0 = g_hA, 1 -> X0 = g_hB. X1 is always g_agg.
// mode 0: write g_hB[m*128 + c]          (node-major intermediate)
// mode 1: write out_ext[(bt*NNODES+n)*128 + c], m = n*4 + bt  (final [B,T,N,F])
__global__ void __launch_bounds__(256, 2)
gemm_kernel(int x_sel,
            const float* __restrict__ Wself, const float* __restrict__ Wneigh,
            const float* __restrict__ bias, float* __restrict__ out_ext,
            int mode) {
    __shared__ __align__(16) float Ws[32 * 128];   // [k][c]
    __shared__ __align__(16) float Xs[32 * 132];   // [k][row], padded stride

    const float* X0 = (x_sel == 0) ? g_hA : g_hB;
    const float* X1 = g_agg;

    int tid = threadIdx.x;
    int tx = tid & 15;        // col group
    int ty = tid >> 4;        // row group
    int tile = blockIdx.x * 128;

    unsigned long long acc[4][8];
#pragma unroll
    for (int a = 0; a < 4; a++)
#pragma unroll
        for (int c = 0; c < 8; c++) acc[a][c] = 0ull;

    const float4* x0v = (const float4*)X0;
    const float4* x1v = (const float4*)X1;
    const float4* wsv = (const float4*)Wself;
    const float4* wnv = (const float4*)Wneigh;

    for (int kc = 0; kc < 8; kc++) {               // 8 chunks of 32 over K=256
        // load W chunk [32][128]
#pragma unroll
        for (int i = 0; i < 4; i++) {
            int lin = tid + i * 256;               // float4 idx, 1024 total
            int kloc = lin >> 5;
            int c4 = lin & 31;
            int kg = kc * 32 + kloc;
            float4 w = (kg < 128) ? wsv[kg * 32 + c4] : wnv[(kg - 128) * 32 + c4];
            ((float4*)Ws)[kloc * 32 + c4] = w;
        }
        // load X chunk transposed: Xs[k][row]
#pragma unroll
        for (int i = 0; i < 4; i++) {
            int lin = tid + i * 256;               // 1024 float4 total
            int row = lin >> 3;                    // 0..127
            int k4 = lin & 7;                      // float4 within 32-k chunk
            int m = tile + row;
            float4 v = make_float4(0.f, 0.f, 0.f, 0.f);
            if (m < MROWS) {
                int k4g = kc * 8 + k4;             // global float4 k index (0..63)
                v = (k4g < 32) ? x0v[m * 32 + k4g] : x1v[m * 32 + (k4g - 32)];
            }
            int kb = k4 * 4;
            Xs[(kb + 0) * 132 + row] = v.x;
            Xs[(kb + 1) * 132 + row] = v.y;
            Xs[(kb + 2) * 132 + row] = v.z;
            Xs[(kb + 3) * 132 + row] = v.w;
        }
        __syncthreads();

#pragma unroll 4
        for (int kk = 0; kk < 32; kk++) {
            // x row pairs: rows ty*4..+3 and 64+ty*4..+3
            ulonglong2 xa = *(const ulonglong2*)&Xs[kk * 132 + ty * 4];
            ulonglong2 xb = *(const ulonglong2*)&Xs[kk * 132 + 64 + ty * 4];
            // W cols tx*4..+3 and 64+tx*4..+3
            float4 wa = *(const float4*)&Ws[kk * 128 + tx * 4];
            float4 wb = *(const float4*)&Ws[kk * 128 + 64 + tx * 4];
            unsigned long long wp[8];
            wp[0] = pack2(wa.x); wp[1] = pack2(wa.y);
            wp[2] = pack2(wa.z); wp[3] = pack2(wa.w);
            wp[4] = pack2(wb.x); wp[5] = pack2(wb.y);
            wp[6] = pack2(wb.z); wp[7] = pack2(wb.w);
#pragma unroll
            for (int c = 0; c < 8; c++) {
                ffma2(acc[0][c], xa.x, wp[c]);
                ffma2(acc[1][c], xa.y, wp[c]);
                ffma2(acc[2][c], xb.x, wp[c]);
                ffma2(acc[3][c], xb.y, wp[c]);
            }
        }
        __syncthreads();
    }

    // epilogue
    float bc[8];
#pragma unroll
    for (int j = 0; j < 4; j++) {
        bc[j] = bias[tx * 4 + j];
        bc[4 + j] = bias[64 + tx * 4 + j];
    }
#pragma unroll
    for (int rp = 0; rp < 4; rp++) {
        int rbase = (rp < 2) ? (ty * 4 + rp * 2) : (64 + ty * 4 + (rp - 2) * 2);
#pragma unroll
        for (int hl = 0; hl < 2; hl++) {
            int m = tile + rbase + hl;
            if (m >= MROWS) continue;
            float v[8];
#pragma unroll
            for (int c = 0; c < 8; c++)
                v[c] = (hl ? hi32(acc[rp][c]) : lo32(acc[rp][c])) + bc[c];
            float* op;
            if (mode == 0) {
                op = g_hB + (size_t)m * 128;
            } else {
                int n = m >> 2;
                int bt = m & 3;
                op = out_ext + ((size_t)bt * NNODES + n) * 128;
            }
            float4 o0 = make_float4(v[0], v[1], v[2], v[3]);
            float4 o1 = make_float4(v[4], v[5], v[6], v[7]);
            *(float4*)(op + tx * 4) = o0;
            *(float4*)(op + 64 + tx * 4) = o1;
        }
    }
}

// ---------------- launch ----------------
extern "C" void kernel_launch(void* const* d_in, const int* in_sizes, int n_in,
                              void* d_out, int out_size) {
    const float* feat   = (const float*)d_in[0];
    const float* Wself  = (const float*)d_in[1];
    const float* Wneigh = (const float*)d_in[2];
    const float* bias   = (const float*)d_in[3];
    const int*   esrc   = (const int*)d_in[4];
    const int*   edst   = (const int*)d_in[5];
    int E = in_sizes[4];

    // CSR build (per call; graph-capturable)
    init_kernel<<<(NNODES + 255) / 256, 256>>>();
    transpose_in_kernel<<<(NNODES * ROW / 4 + 255) / 256, 256>>>(feat);
    degree_kernel<<<(E + 255) / 256, 256>>>(edst, E);
    scan_kernel<<<1, 1024>>>(E);
    bucket_kernel<<<(E + 255) / 256, 256>>>(esrc, edst, E);

    int gtiles = (MROWS + 127) / 128;   // 313

    // layer 0: read g_hA, agg -> g_agg, gemm -> g_hB
    agg_kernel<<<NNODES, 128>>>(0);
    gemm_kernel<<<gtiles, 256>>>(0, Wself, Wneigh, bias, (float*)d_out, 0);

    // layer 1: read g_hB, agg -> g_agg, gemm -> d_out (final [B,T,N,F] layout)
    agg_kernel<<<NNODES, 128>>>(1);
    gemm_kernel<<<gtiles, 256>>>(1, Wself + 128 * 128, Wneigh + 128 * 128,
                                 bias + 128, (float*)d_out, 1);
}

// round 4
// speedup vs baseline: 1.3555x; 1.3555x over previous
#include <cuda_runtime.h>
#include <cuda_bf16.h>
#include <cstdint>

// Problem constants (fixed shapes for this problem instance)
#define NNODES 10000
#define BT 4            // B*T
#define FDIM 128
#define ROW (BT*FDIM)   // 512 floats per node row
#define EMAX 262144
#define MROWS (NNODES*BT)   // 40000 GEMM rows

// GEMM smem layout (32-bit word offsets into dynamic smem)
#define BKS 132                 // B plane row stride in words (128 kpairs + 4 pad)
#define AKS 36                  // A plane row stride in words (32 kpairs + 4 pad)
#define B_HI_OFF 0
#define B_LO_OFF (128*BKS)              // 16896
#define A_HI_OFF (2*128*BKS)            // 33792
#define A_LO_OFF (A_HI_OFF + 128*AKS)   // 38400
#define BIAS_OFF (A_LO_OFF + 128*AKS)   // 43008
#define GSMEM_WORDS (BIAS_OFF + 128)    // 43136
#define GSMEM_BYTES (GSMEM_WORDS*4)     // 172544

// ---------------- device scratch (no allocation allowed) ----------------
__device__ float g_hA[NNODES*ROW];
__device__ float g_hB[NNODES*ROW];
__device__ float g_agg[NNODES*ROW];
__device__ float g_WT[2*128*256];     // per layer: [n(out col)][k(0:128 self,128:256 neigh)]
__device__ int   g_deg[NNODES];
__device__ int   g_cursor[NNODES];
__device__ int   g_off[NNODES+1];
__device__ float g_invdeg[NNODES];
__device__ int   g_esrc_sorted[EMAX];

// ---------------- helpers ----------------
// split a,b into packed bf16 hi pair and lo pair (low half = first element)
__device__ __forceinline__ void split2(float a, float b, uint32_t& hi, uint32_t& lo) {
    __nv_bfloat16 ha = __float2bfloat16_rn(a);
    __nv_bfloat16 hb = __float2bfloat16_rn(b);
    float ra = a - __bfloat162float(ha);
    float rb = b - __bfloat162float(hb);
    __nv_bfloat16 la = __float2bfloat16_rn(ra);
    __nv_bfloat16 lb = __float2bfloat16_rn(rb);
    hi = ((uint32_t)__bfloat16_as_ushort(hb) << 16) | (uint32_t)__bfloat16_as_ushort(ha);
    lo = ((uint32_t)__bfloat16_as_ushort(lb) << 16) | (uint32_t)__bfloat16_as_ushort(la);
}

__device__ __forceinline__ void mma_bf16(float* c, const uint32_t* a,
                                         uint32_t b0, uint32_t b1) {
    asm volatile(
        "mma.sync.aligned.m16n8k16.row.col.f32.bf16.bf16.f32 "
        "{%0,%1,%2,%3}, {%4,%5,%6,%7}, {%8,%9}, {%0,%1,%2,%3};"
        : "+f"(c[0]), "+f"(c[1]), "+f"(c[2]), "+f"(c[3])
        : "r"(a[0]), "r"(a[1]), "r"(a[2]), "r"(a[3]), "r"(b0), "r"(b1));
}

// ---------------- setup kernels ----------------
__global__ void init_kernel() {
    int i = blockIdx.x * blockDim.x + threadIdx.x;
    if (i < NNODES) { g_deg[i] = 0; g_cursor[i] = 0; }
}

// feature [B,T,N,F] -> g_hA [N, BT, F]
__global__ void transpose_in_kernel(const float* __restrict__ feat) {
    int j = blockIdx.x * blockDim.x + threadIdx.x;
    const int TOT = NNODES * ROW / 4;
    if (j >= TOT) return;
    int n = j >> 7;
    int rem = j & 127;
    int bt = rem >> 5;
    int f4 = rem & 31;
    ((float4*)g_hA)[j] = ((const float4*)feat)[(bt * NNODES + n) * 32 + f4];
}

// W_self[l][k][n], W_neigh[l][k][n] -> g_WT[l][n][k] (k in 0..255, concat)
__global__ void wt_kernel(const float* __restrict__ Wself,
                          const float* __restrict__ Wneigh) {
    int idx = blockIdx.x * blockDim.x + threadIdx.x;   // 2*128*256 = 65536
    if (idx >= 2 * 128 * 256) return;
    int l = idx >> 15;
    int rem = idx & 32767;
    int n = rem >> 8;
    int k = rem & 255;
    float w = (k < 128) ? Wself[l * 16384 + k * 128 + n]
                        : Wneigh[l * 16384 + (k - 128) * 128 + n];
    g_WT[(l * 128 + n) * 256 + k] = w;
}

__global__ void degree_kernel(const int* __restrict__ edst, int E) {
    int e = blockIdx.x * blockDim.x + threadIdx.x;
    if (e < E) atomicAdd(&g_deg[edst[e]], 1);
}

// fast single-CTA scan: 10 elems/thread + warp/block shuffle scan
__global__ void __launch_bounds__(1024) scan_kernel(int E) {
    __shared__ int wsum[32];
    int tid = threadIdx.x;
    int lane = tid & 31;
    int w = tid >> 5;
    int base = tid * 10;
    int d[10];
    int tot = 0;
#pragma unroll
    for (int j = 0; j < 10; j++) {
        int idx = base + j;
        d[j] = (idx < NNODES) ? g_deg[idx] : 0;
        tot += d[j];
    }
    int inc = tot;
#pragma unroll
    for (int off = 1; off < 32; off <<= 1) {
        int nv = __shfl_up_sync(0xffffffffu, inc, off);
        if (lane >= off) inc += nv;
    }
    if (lane == 31) wsum[w] = inc;
    __syncthreads();
    if (w == 0) {
        int v = wsum[lane];
        int i2 = v;
#pragma unroll
        for (int off = 1; off < 32; off <<= 1) {
            int nv = __shfl_up_sync(0xffffffffu, i2, off);
            if (lane >= off) i2 += nv;
        }
        wsum[lane] = i2 - v;   // exclusive warp offsets
    }
    __syncthreads();
    int run = wsum[w] + inc - tot;
#pragma unroll
    for (int j = 0; j < 10; j++) {
        int idx = base + j;
        if (idx < NNODES) {
            g_off[idx] = run;
            g_invdeg[idx] = (d[j] > 0) ? (1.0f / (float)d[j]) : 0.0f;
        }
        run += d[j];
    }
    if (tid == 0) g_off[NNODES] = E;
}

__global__ void bucket_kernel(const int* __restrict__ esrc,
                              const int* __restrict__ edst, int E) {
    int e = blockIdx.x * blockDim.x + threadIdx.x;
    if (e < E) {
        int dnode = edst[e];
        int p = g_off[dnode] + atomicAdd(&g_cursor[dnode], 1);
        g_esrc_sorted[p] = esrc[e];
    }
}

// ---------------- mean aggregation: one CTA per dst node ----------------
__global__ void __launch_bounds__(128) agg_kernel(int src_sel) {
    const float* hin = (src_sel == 0) ? g_hA : g_hB;
    int n = blockIdx.x;
    int t = threadIdx.x;
    int s = g_off[n];
    int e = g_off[n + 1];
    const float4* hv = (const float4*)hin;
    float4 a0 = make_float4(0.f, 0.f, 0.f, 0.f);
    float4 a1 = make_float4(0.f, 0.f, 0.f, 0.f);
    int i = s;
    for (; i + 1 < e; i += 2) {
        int s0 = g_esrc_sorted[i];
        int s1 = g_esrc_sorted[i + 1];
        float4 v0 = hv[s0 * 128 + t];
        float4 v1 = hv[s1 * 128 + t];
        a0.x += v0.x; a0.y += v0.y; a0.z += v0.z; a0.w += v0.w;
        a1.x += v1.x; a1.y += v1.y; a1.z += v1.z; a1.w += v1.w;
    }
    if (i < e) {
        int s0 = g_esrc_sorted[i];
        float4 v0 = hv[s0 * 128 + t];
        a0.x += v0.x; a0.y += v0.y; a0.z += v0.z; a0.w += v0.w;
    }
    float inv = g_invdeg[n];
    float4 r;
    r.x = (a0.x + a1.x) * inv;
    r.y = (a0.y + a1.y) * inv;
    r.z = (a0.z + a1.z) * inv;
    r.w = (a0.w + a1.w) * inv;
    ((float4*)g_agg)[n * 128 + t] = r;
}

// ---------------- mma.sync bf16x2-split GEMM ----------------
// out[m][n] = sum_k X[m][k]*W[k][n] + b[n]; M=40000, K=256, N=128.
// X: k<128 from X0 (g_hA/g_hB), k>=128 from g_agg. B = g_WT[layer] [n][k].
// 128x128 tile/CTA, 8 warps (4 row x 2 col), warp tile 32x64.
// 2-term bf16 split, 3 products (hh, hl, lh), fp32 accum via mma.sync.
__global__ void __launch_bounds__(256) gemm_mma(int x_sel, int layer,
                                                const float* __restrict__ bias,
                                                float* __restrict__ out_ext,
                                                int mode) {
    extern __shared__ uint32_t sm[];
    uint32_t* Bhi = sm + B_HI_OFF;
    uint32_t* Blo = sm + B_LO_OFF;
    uint32_t* Ahi = sm + A_HI_OFF;
    uint32_t* Alo = sm + A_LO_OFF;
    float* sbias = (float*)(sm + BIAS_OFF);

    int tid = threadIdx.x;
    int lane = tid & 31;
    int warp = tid >> 5;
    int g = lane >> 2;        // group 0..7
    int t = lane & 3;         // thread-in-group 0..3
    int wr = (warp & 3) * 32; // warp row base
    int wc = (warp >> 2) * 64;// warp col base
    int tile = blockIdx.x * 128;

    if (tid < 128) sbias[tid] = bias[tid];

    // stage B (whole K) with bf16 split: 8192 float4, 32 per thread
    const float4* wv = (const float4*)(g_WT + layer * 128 * 256);
#pragma unroll
    for (int i = 0; i < 32; i++) {
        int lin = tid + i * 256;
        int n = lin >> 6;
        int j = lin & 63;            // float4 index within row (k = 4j)
        float4 v = wv[n * 64 + j];
        uint32_t h0, l0, h1, l1;
        split2(v.x, v.y, h0, l0);
        split2(v.z, v.w, h1, l1);
        *(uint2*)&Bhi[n * BKS + 2 * j] = make_uint2(h0, h1);
        *(uint2*)&Blo[n * BKS + 2 * j] = make_uint2(l0, l1);
    }

    const float4* x0v = (const float4*)((x_sel == 0) ? g_hA : g_hB);
    const float4* x1v = (const float4*)g_agg;

    float acc[2][8][4];
#pragma unroll
    for (int rb = 0; rb < 2; rb++)
#pragma unroll
        for (int nb = 0; nb < 8; nb++)
#pragma unroll
            for (int c = 0; c < 4; c++) acc[rb][nb][c] = 0.f;

    for (int kc = 0; kc < 4; kc++) {          // 4 chunks of K=64
        // stage A chunk: 2048 float4, 8 per thread
#pragma unroll
        for (int i = 0; i < 8; i++) {
            int lin = tid + i * 256;
            int row = lin >> 4;
            int j = lin & 15;                 // float4 within chunk (k = 4j)
            int m = tile + row;
            if (m >= MROWS) m = MROWS - 1;
            int j4 = kc * 16 + j;             // global float4 k index 0..63
            float4 v = (j4 < 32) ? x0v[m * 32 + j4] : x1v[m * 32 + (j4 - 32)];
            uint32_t h0, l0, h1, l1;
            split2(v.x, v.y, h0, l0);
            split2(v.z, v.w, h1, l1);
            *(uint2*)&Ahi[row * AKS + 2 * j] = make_uint2(h0, h1);
            *(uint2*)&Alo[row * AKS + 2 * j] = make_uint2(l0, l1);
        }
        __syncthreads();

#pragma unroll
        for (int ks = 0; ks < 4; ks++) {      // 4 k16-steps per chunk
            int kb = ks * 8;                  // kpair base within chunk
            int gb = kc * 32 + kb;            // kpair base global (B)
            uint32_t ah[2][4], al[2][4];
#pragma unroll
            for (int rb = 0; rb < 2; rb++) {
                int r0 = (wr + rb * 16 + g) * AKS;
                int r1 = r0 + 8 * AKS;
                ah[rb][0] = Ahi[r0 + kb + t];
                ah[rb][1] = Ahi[r1 + kb + t];
                ah[rb][2] = Ahi[r0 + kb + t + 4];
                ah[rb][3] = Ahi[r1 + kb + t + 4];
                al[rb][0] = Alo[r0 + kb + t];
                al[rb][1] = Alo[r1 + kb + t];
                al[rb][2] = Alo[r0 + kb + t + 4];
                al[rb][3] = Alo[r1 + kb + t + 4];
            }
#pragma unroll
            for (int nb = 0; nb < 8; nb++) {
                int boff = (wc + nb * 8 + g) * BKS + gb;
                uint32_t bh0 = Bhi[boff + t];
                uint32_t bh1 = Bhi[boff + t + 4];
                uint32_t bl0 = Blo[boff + t];
                uint32_t bl1 = Blo[boff + t + 4];
#pragma unroll
                for (int rb = 0; rb < 2; rb++) {
                    mma_bf16(acc[rb][nb], ah[rb], bh0, bh1);
                    mma_bf16(acc[rb][nb], ah[rb], bl0, bl1);
                    mma_bf16(acc[rb][nb], al[rb], bh0, bh1);
                }
            }
        }
        __syncthreads();
    }

    // epilogue: c0=(g,2t) c1=(g,2t+1) c2=(g+8,2t) c3=(g+8,2t+1)
#pragma unroll
    for (int rb = 0; rb < 2; rb++) {
#pragma unroll
        for (int h = 0; h < 2; h++) {
            int m = tile + wr + rb * 16 + g + h * 8;
            if (m < MROWS) {
                float* op;
                if (mode == 0) {
                    op = g_hB + (size_t)m * 128;
                } else {
                    int n = m >> 2;
                    int bt = m & 3;
                    op = out_ext + ((size_t)bt * NNODES + n) * 128;
                }
#pragma unroll
                for (int nb = 0; nb < 8; nb++) {
                    int col = wc + nb * 8 + 2 * t;
                    float2 v;
                    v.x = acc[rb][nb][h * 2 + 0] + sbias[col];
                    v.y = acc[rb][nb][h * 2 + 1] + sbias[col + 1];
                    *(float2*)(op + col) = v;
                }
            }
        }
    }
}

// ---------------- launch ----------------
extern "C" void kernel_launch(void* const* d_in, const int* in_sizes, int n_in,
                              void* d_out, int out_size) {
    const float* feat   = (const float*)d_in[0];
    const float* Wself  = (const float*)d_in[1];
    const float* Wneigh = (const float*)d_in[2];
    const float* bias   = (const float*)d_in[3];
    const int*   esrc   = (const int*)d_in[4];
    const int*   edst   = (const int*)d_in[5];
    int E = in_sizes[4];

    cudaFuncSetAttribute(gemm_mma, cudaFuncAttributeMaxDynamicSharedMemorySize,
                         GSMEM_BYTES);

    init_kernel<<<(NNODES + 255) / 256, 256>>>();
    transpose_in_kernel<<<(NNODES * ROW / 4 + 255) / 256, 256>>>(feat);
    wt_kernel<<<(2 * 128 * 256 + 255) / 256, 256>>>(Wself, Wneigh);
    degree_kernel<<<(E + 255) / 256, 256>>>(edst, E);
    scan_kernel<<<1, 1024>>>(E);
    bucket_kernel<<<(E + 255) / 256, 256>>>(esrc, edst, E);

    int gtiles = (MROWS + 127) / 128;   // 313

    // layer 0: read g_hA, agg -> g_agg, gemm -> g_hB
    agg_kernel<<<NNODES, 128>>>(0);
    gemm_mma<<<gtiles, 256, GSMEM_BYTES>>>(0, 0, bias, (float*)d_out, 0);

    // layer 1: read g_hB, agg -> g_agg, gemm -> d_out (final [B,T,N,F])
    agg_kernel<<<NNODES, 128>>>(1);
    gemm_mma<<<gtiles, 256, GSMEM_BYTES>>>(1, 1, bias + 128, (float*)d_out, 1);
}

// round 5
// speedup vs baseline: 1.4446x; 1.0657x over previous
#include <cuda_runtime.h>
#include <cuda_bf16.h>
#include <cstdint>

// Problem constants (fixed shapes for this problem instance)
#define NNODES 10000
#define BT 4            // B*T
#define FDIM 128
#define ROW (BT*FDIM)   // 512 floats per node row
#define EMAX 262144
#define MROWS (NNODES*BT)   // 40000 GEMM rows

// GEMM smem layout (32-bit word offsets into dynamic smem)
#define BKS 132                 // B plane row stride in words (128 kpairs + 4 pad)
#define AKS 36                  // A plane row stride in words (32 kpairs + 4 pad)
#define ABUF (128*AKS)          // 4608 words per A buffer
#define B_HI_OFF 0
#define B_LO_OFF (128*BKS)              // 16896
#define A_HI_OFF (2*128*BKS)            // 33792 (2 buffers, 9216 words)
#define A_LO_OFF (A_HI_OFF + 2*ABUF)    // 43008 (2 buffers)
#define BIAS_OFF (A_LO_OFF + 2*ABUF)    // 52224
#define GSMEM_WORDS (BIAS_OFF + 128)    // 52352
#define GSMEM_BYTES (GSMEM_WORDS*4)     // 209408

// ---------------- device scratch (no allocation allowed) ----------------
__device__ float g_hA[NNODES*ROW];
__device__ float g_hB[NNODES*ROW];
__device__ float g_agg[NNODES*ROW];
__device__ uint32_t g_WThi[2*128*128];  // per layer: [n][kpair] bf16x2 hi plane
__device__ uint32_t g_WTlo[2*128*128];  // per layer: [n][kpair] bf16x2 lo plane
__device__ int   g_deg[NNODES];
__device__ int   g_cursor[NNODES];
__device__ int   g_off[NNODES+1];
__device__ float g_invdeg[NNODES];
__device__ int   g_esrc_sorted[EMAX];

// ---------------- helpers ----------------
// split a,b into packed bf16 hi pair and lo pair (low half = first element)
__device__ __forceinline__ void split2(float a, float b, uint32_t& hi, uint32_t& lo) {
    __nv_bfloat16 ha = __float2bfloat16_rn(a);
    __nv_bfloat16 hb = __float2bfloat16_rn(b);
    float ra = a - __bfloat162float(ha);
    float rb = b - __bfloat162float(hb);
    __nv_bfloat16 la = __float2bfloat16_rn(ra);
    __nv_bfloat16 lb = __float2bfloat16_rn(rb);
    hi = ((uint32_t)__bfloat16_as_ushort(hb) << 16) | (uint32_t)__bfloat16_as_ushort(ha);
    lo = ((uint32_t)__bfloat16_as_ushort(lb) << 16) | (uint32_t)__bfloat16_as_ushort(la);
}

__device__ __forceinline__ void mma_bf16(float* c, const uint32_t* a,
                                         uint32_t b0, uint32_t b1) {
    asm volatile(
        "mma.sync.aligned.m16n8k16.row.col.f32.bf16.bf16.f32 "
        "{%0,%1,%2,%3}, {%4,%5,%6,%7}, {%8,%9}, {%0,%1,%2,%3};"
        : "+f"(c[0]), "+f"(c[1]), "+f"(c[2]), "+f"(c[3])
        : "r"(a[0]), "r"(a[1]), "r"(a[2]), "r"(a[3]), "r"(b0), "r"(b1));
}

// ---------------- setup kernels ----------------
__global__ void init_kernel() {
    int i = blockIdx.x * blockDim.x + threadIdx.x;
    if (i < NNODES) { g_deg[i] = 0; g_cursor[i] = 0; }
}

// feature [B,T,N,F] -> g_hA [N, BT, F]
__global__ void transpose_in_kernel(const float* __restrict__ feat) {
    int j = blockIdx.x * blockDim.x + threadIdx.x;
    const int TOT = NNODES * ROW / 4;
    if (j >= TOT) return;
    int n = j >> 7;
    int rem = j & 127;
    int bt = rem >> 5;
    int f4 = rem & 31;
    ((float4*)g_hA)[j] = ((const float4*)feat)[(bt * NNODES + n) * 32 + f4];
}

// W_self[l][k][n], W_neigh[l][k][n] -> pre-split bf16 planes [l][n][kpair]
__global__ void wt_kernel(const float* __restrict__ Wself,
                          const float* __restrict__ Wneigh) {
    int idx = blockIdx.x * blockDim.x + threadIdx.x;   // 2*128*128 = 32768 kpairs
    if (idx >= 2 * 128 * 128) return;
    int l = idx >> 14;
    int rem = idx & 16383;
    int n = rem >> 7;
    int kp = rem & 127;
    float w0, w1;
    if (kp < 64) {
        int k = 2 * kp;
        w0 = Wself[l * 16384 + k * 128 + n];
        w1 = Wself[l * 16384 + (k + 1) * 128 + n];
    } else {
        int k = 2 * kp - 128;
        w0 = Wneigh[l * 16384 + k * 128 + n];
        w1 = Wneigh[l * 16384 + (k + 1) * 128 + n];
    }
    uint32_t hi, lo;
    split2(w0, w1, hi, lo);
    g_WThi[idx] = hi;
    g_WTlo[idx] = lo;
}

// 4 edges per thread via int4
__global__ void degree_kernel(const int* __restrict__ edst, int E) {
    int e4 = blockIdx.x * blockDim.x + threadIdx.x;
    int n4 = E >> 2;
    if (e4 < n4) {
        int4 v = ((const int4*)edst)[e4];
        atomicAdd(&g_deg[v.x], 1);
        atomicAdd(&g_deg[v.y], 1);
        atomicAdd(&g_deg[v.z], 1);
        atomicAdd(&g_deg[v.w], 1);
    }
    if (e4 == 0) {
        for (int e = n4 * 4; e < E; e++) atomicAdd(&g_deg[edst[e]], 1);
    }
}

// fast single-CTA scan: 10 elems/thread + warp/block shuffle scan
__global__ void __launch_bounds__(1024) scan_kernel(int E) {
    __shared__ int wsum[32];
    int tid = threadIdx.x;
    int lane = tid & 31;
    int w = tid >> 5;
    int base = tid * 10;
    int d[10];
    int tot = 0;
#pragma unroll
    for (int j = 0; j < 10; j++) {
        int idx = base + j;
        d[j] = (idx < NNODES) ? g_deg[idx] : 0;
        tot += d[j];
    }
    int inc = tot;
#pragma unroll
    for (int off = 1; off < 32; off <<= 1) {
        int nv = __shfl_up_sync(0xffffffffu, inc, off);
        if (lane >= off) inc += nv;
    }
    if (lane == 31) wsum[w] = inc;
    __syncthreads();
    if (w == 0) {
        int v = wsum[lane];
        int i2 = v;
#pragma unroll
        for (int off = 1; off < 32; off <<= 1) {
            int nv = __shfl_up_sync(0xffffffffu, i2, off);
            if (lane >= off) i2 += nv;
        }
        wsum[lane] = i2 - v;   // exclusive warp offsets
    }
    __syncthreads();
    int run = wsum[w] + inc - tot;
#pragma unroll
    for (int j = 0; j < 10; j++) {
        int idx = base + j;
        if (idx < NNODES) {
            g_off[idx] = run;
            g_invdeg[idx] = (d[j] > 0) ? (1.0f / (float)d[j]) : 0.0f;
        }
        run += d[j];
    }
    if (tid == 0) g_off[NNODES] = E;
}

__global__ void bucket_kernel(const int* __restrict__ esrc,
                              const int* __restrict__ edst, int E) {
    int e4 = blockIdx.x * blockDim.x + threadIdx.x;
    int n4 = E >> 2;
    if (e4 < n4) {
        int4 s = ((const int4*)esrc)[e4];
        int4 d = ((const int4*)edst)[e4];
        int p;
        p = g_off[d.x] + atomicAdd(&g_cursor[d.x], 1); g_esrc_sorted[p] = s.x;
        p = g_off[d.y] + atomicAdd(&g_cursor[d.y], 1); g_esrc_sorted[p] = s.y;
        p = g_off[d.z] + atomicAdd(&g_cursor[d.z], 1); g_esrc_sorted[p] = s.z;
        p = g_off[d.w] + atomicAdd(&g_cursor[d.w], 1); g_esrc_sorted[p] = s.w;
    }
    if (e4 == 0) {
        for (int e = n4 * 4; e < E; e++) {
            int dn = edst[e];
            int p = g_off[dn] + atomicAdd(&g_cursor[dn], 1);
            g_esrc_sorted[p] = esrc[e];
        }
    }
}

// ---------------- mean aggregation: one CTA per dst node ----------------
__global__ void __launch_bounds__(128) agg_kernel(int src_sel) {
    const float* hin = (src_sel == 0) ? g_hA : g_hB;
    int n = blockIdx.x;
    int t = threadIdx.x;
    int s = g_off[n];
    int e = g_off[n + 1];
    const float4* hv = (const float4*)hin;
    float4 a0 = make_float4(0.f, 0.f, 0.f, 0.f);
    float4 a1 = make_float4(0.f, 0.f, 0.f, 0.f);
    float4 a2 = make_float4(0.f, 0.f, 0.f, 0.f);
    float4 a3 = make_float4(0.f, 0.f, 0.f, 0.f);
    int i = s;
    for (; i + 3 < e; i += 4) {
        int s0 = g_esrc_sorted[i];
        int s1 = g_esrc_sorted[i + 1];
        int s2 = g_esrc_sorted[i + 2];
        int s3 = g_esrc_sorted[i + 3];
        float4 v0 = hv[s0 * 128 + t];
        float4 v1 = hv[s1 * 128 + t];
        float4 v2 = hv[s2 * 128 + t];
        float4 v3 = hv[s3 * 128 + t];
        a0.x += v0.x; a0.y += v0.y; a0.z += v0.z; a0.w += v0.w;
        a1.x += v1.x; a1.y += v1.y; a1.z += v1.z; a1.w += v1.w;
        a2.x += v2.x; a2.y += v2.y; a2.z += v2.z; a2.w += v2.w;
        a3.x += v3.x; a3.y += v3.y; a3.z += v3.z; a3.w += v3.w;
    }
    for (; i < e; i++) {
        int s0 = g_esrc_sorted[i];
        float4 v0 = hv[s0 * 128 + t];
        a0.x += v0.x; a0.y += v0.y; a0.z += v0.z; a0.w += v0.w;
    }
    float inv = g_invdeg[n];
    float4 r;
    r.x = (a0.x + a1.x + a2.x + a3.x) * inv;
    r.y = (a0.y + a1.y + a2.y + a3.y) * inv;
    r.z = (a0.z + a1.z + a2.z + a3.z) * inv;
    r.w = (a0.w + a1.w + a2.w + a3.w) * inv;
    ((float4*)g_agg)[n * 128 + t] = r;
}

// ---------------- mma.sync bf16x2-split GEMM (pipelined) ----------------
// out[m][n] = sum_k X[m][k]*W[k][n] + b[n]; M=40000, K=256, N=128.
// B pre-split in global (g_WThi/g_WTlo) -> straight copy into smem.
// A: fp32 load + split, double-buffered, next-chunk loads issued before MMAs.
__global__ void __launch_bounds__(256) gemm_mma(int x_sel, int layer,
                                                const float* __restrict__ bias,
                                                float* __restrict__ out_ext,
                                                int mode) {
    extern __shared__ uint32_t sm[];
    uint32_t* Bhi = sm + B_HI_OFF;
    uint32_t* Blo = sm + B_LO_OFF;
    float* sbias = (float*)(sm + BIAS_OFF);

    int tid = threadIdx.x;
    int lane = tid & 31;
    int warp = tid >> 5;
    int g = lane >> 2;        // group 0..7
    int t = lane & 3;         // thread-in-group 0..3
    int wr = (warp & 3) * 32; // warp row base
    int wc = (warp >> 2) * 64;// warp col base
    int tile = blockIdx.x * 128;

    if (tid < 128) sbias[tid] = bias[tid];

    // stage B: straight uint4 copy of pre-split planes (4096 uint4 per plane)
    const uint4* bhv = (const uint4*)(g_WThi + layer * 128 * 128);
    const uint4* blv = (const uint4*)(g_WTlo + layer * 128 * 128);
#pragma unroll
    for (int i = 0; i < 16; i++) {
        int lin = tid + i * 256;
        int n = lin >> 5;            // row 0..127
        int j = lin & 31;            // uint4 within row (kpair = 4j)
        *(uint4*)&Bhi[n * BKS + 4 * j] = bhv[lin];
        *(uint4*)&Blo[n * BKS + 4 * j] = blv[lin];
    }

    const float4* x0v = (const float4*)((x_sel == 0) ? g_hA : g_hB);
    const float4* x1v = (const float4*)g_agg;

    // A staging addressing (fixed per thread)
    int arow = tid >> 4;             // handles rows arow, with 8 j-slots
    float acc[2][8][4];
#pragma unroll
    for (int rb = 0; rb < 2; rb++)
#pragma unroll
        for (int nb = 0; nb < 8; nb++)
#pragma unroll
            for (int c = 0; c < 4; c++) acc[rb][nb][c] = 0.f;

    // preload chunk 0 (8 float4 per thread)
    float4 v[8];
#pragma unroll
    for (int i = 0; i < 8; i++) {
        int lin = tid + i * 256;
        int row = lin >> 4;
        int j = lin & 15;
        int m = tile + row;
        if (m >= MROWS) m = MROWS - 1;
        int j4 = j;                  // kc=0
        v[i] = (j4 < 32) ? x0v[m * 32 + j4] : x1v[m * 32 + (j4 - 32)];
    }

    for (int kc = 0; kc < 4; kc++) {          // 4 chunks of K=64
        uint32_t* Ahi = sm + A_HI_OFF + (kc & 1) * ABUF;
        uint32_t* Alo = sm + A_LO_OFF + (kc & 1) * ABUF;
        // split & store current chunk
#pragma unroll
        for (int i = 0; i < 8; i++) {
            int lin = tid + i * 256;
            int row = lin >> 4;
            int j = lin & 15;
            uint32_t h0, l0, h1, l1;
            split2(v[i].x, v[i].y, h0, l0);
            split2(v[i].z, v[i].w, h1, l1);
            *(uint2*)&Ahi[row * AKS + 2 * j] = make_uint2(h0, h1);
            *(uint2*)&Alo[row * AKS + 2 * j] = make_uint2(l0, l1);
        }
        __syncthreads();

        // issue next chunk's global loads (latency hidden by MMAs below)
        if (kc < 3) {
#pragma unroll
            for (int i = 0; i < 8; i++) {
                int lin = tid + i * 256;
                int row = lin >> 4;
                int j = lin & 15;
                int m = tile + row;
                if (m >= MROWS) m = MROWS - 1;
                int j4 = (kc + 1) * 16 + j;
                v[i] = (j4 < 32) ? x0v[m * 32 + j4] : x1v[m * 32 + (j4 - 32)];
            }
        }

#pragma unroll
        for (int ks = 0; ks < 4; ks++) {      // 4 k16-steps per chunk
            int kb = ks * 8;                  // kpair base within chunk
            int gb = kc * 32 + kb;            // kpair base global (B)
            uint32_t ah[2][4], al[2][4];
#pragma unroll
            for (int rb = 0; rb < 2; rb++) {
                int r0 = (wr + rb * 16 + g) * AKS;
                int r1 = r0 + 8 * AKS;
                ah[rb][0] = Ahi[r0 + kb + t];
                ah[rb][1] = Ahi[r1 + kb + t];
                ah[rb][2] = Ahi[r0 + kb + t + 4];
                ah[rb][3] = Ahi[r1 + kb + t + 4];
                al[rb][0] = Alo[r0 + kb + t];
                al[rb][1] = Alo[r1 + kb + t];
                al[rb][2] = Alo[r0 + kb + t + 4];
                al[rb][3] = Alo[r1 + kb + t + 4];
            }
#pragma unroll
            for (int nb = 0; nb < 8; nb++) {
                int boff = (wc + nb * 8 + g) * BKS + gb;
                uint32_t bh0 = Bhi[boff + t];
                uint32_t bh1 = Bhi[boff + t + 4];
                uint32_t bl0 = Blo[boff + t];
                uint32_t bl1 = Blo[boff + t + 4];
#pragma unroll
                for (int rb = 0; rb < 2; rb++) {
                    mma_bf16(acc[rb][nb], ah[rb], bh0, bh1);
                    mma_bf16(acc[rb][nb], ah[rb], bl0, bl1);
                    mma_bf16(acc[rb][nb], al[rb], bh0, bh1);
                }
            }
        }
        // no trailing sync: next iteration writes the other A buffer; the
        // __syncthreads at its top orders those writes against these reads.
    }

    // epilogue: c0=(g,2t) c1=(g,2t+1) c2=(g+8,2t) c3=(g+8,2t+1)
#pragma unroll
    for (int rb = 0; rb < 2; rb++) {
#pragma unroll
        for (int h = 0; h < 2; h++) {
            int m = tile + wr + rb * 16 + g + h * 8;
            if (m < MROWS) {
                float* op;
                if (mode == 0) {
                    op = g_hB + (size_t)m * 128;
                } else {
                    int n = m >> 2;
                    int bt = m & 3;
                    op = out_ext + ((size_t)bt * NNODES + n) * 128;
                }
#pragma unroll
                for (int nb = 0; nb < 8; nb++) {
                    int col = wc + nb * 8 + 2 * t;
                    float2 vv;
                    vv.x = acc[rb][nb][h * 2 + 0] + sbias[col];
                    vv.y = acc[rb][nb][h * 2 + 1] + sbias[col + 1];
                    *(float2*)(op + col) = vv;
                }
            }
        }
    }
}

// ---------------- launch ----------------
extern "C" void kernel_launch(void* const* d_in, const int* in_sizes, int n_in,
                              void* d_out, int out_size) {
    const float* feat   = (const float*)d_in[0];
    const float* Wself  = (const float*)d_in[1];
    const float* Wneigh = (const float*)d_in[2];
    const float* bias   = (const float*)d_in[3];
    const int*   esrc   = (const int*)d_in[4];
    const int*   edst   = (const int*)d_in[5];
    int E = in_sizes[4];

    cudaFuncSetAttribute(gemm_mma, cudaFuncAttributeMaxDynamicSharedMemorySize,
                         GSMEM_BYTES);

    init_kernel<<<(NNODES + 255) / 256, 256>>>();
    transpose_in_kernel<<<(NNODES * ROW / 4 + 255) / 256, 256>>>(feat);
    wt_kernel<<<(2 * 128 * 128 + 255) / 256, 256>>>(Wself, Wneigh);
    degree_kernel<<<((E / 4) + 255) / 256, 256>>>(edst, E);
    scan_kernel<<<1, 1024>>>(E);
    bucket_kernel<<<((E / 4) + 255) / 256, 256>>>(esrc, edst, E);

    int gtiles = (MROWS + 127) / 128;   // 313

    // layer 0: read g_hA, agg -> g_agg, gemm -> g_hB
    agg_kernel<<<NNODES, 128>>>(0);
    gemm_mma<<<gtiles, 256, GSMEM_BYTES>>>(0, 0, bias, (float*)d_out, 0);

    // layer 1: read g_hB, agg -> g_agg, gemm -> d_out (final [B,T,N,F])
    agg_kernel<<<NNODES, 128>>>(1);
    gemm_mma<<<gtiles, 256, GSMEM_BYTES>>>(1, 1, bias + 128, (float*)d_out, 1);
}

// round 6
// speedup vs baseline: 1.4495x; 1.0034x over previous
#include <cuda_runtime.h>
#include <cuda_bf16.h>
#include <cstdint>

// Problem constants (fixed shapes for this problem instance)
#define NNODES 10000
#define BT 4            // B*T
#define FDIM 128
#define ROW (BT*FDIM)   // 512 floats per node row
#define EMAX 262144
#define MROWS (NNODES*BT)   // 40000 GEMM rows
#define NTILES ((MROWS + 127) / 128)   // 313

// GEMM smem layout (32-bit word offsets into dynamic smem)
#define BKS 132                 // B plane row stride in words (128 kpairs + 4 pad)
#define AKS 36                  // A plane row stride in words (32 kpairs + 4 pad)
#define ABUF (128*AKS)          // 4608 words per A buffer
#define B_HI_OFF 0
#define B_LO_OFF (128*BKS)              // 16896
#define A_HI_OFF (2*128*BKS)            // 33792 (2 buffers)
#define A_LO_OFF (A_HI_OFF + 2*ABUF)    // 43008 (2 buffers)
#define BIAS_OFF (A_LO_OFF + 2*ABUF)    // 52224
#define GSMEM_WORDS (BIAS_OFF + 128)    // 52352
#define GSMEM_BYTES (GSMEM_WORDS*4)     // 209408

// ---------------- device scratch (no allocation allowed) ----------------
__device__ float g_hB[NNODES*ROW];
__device__ float g_agg[NNODES*ROW];
__device__ uint32_t g_WThi[2*128*128];  // per layer: [n][kpair] bf16x2 hi plane
__device__ uint32_t g_WTlo[2*128*128];  // per layer: [n][kpair] bf16x2 lo plane
__device__ int   g_deg[NNODES];
__device__ int   g_cursor[NNODES];
__device__ int   g_off[NNODES+1];
__device__ float g_invdeg[NNODES];
__device__ int   g_esrc_sorted[EMAX];
__device__ int   g_tilectr[2];

// ---------------- helpers ----------------
__device__ __forceinline__ void split2(float a, float b, uint32_t& hi, uint32_t& lo) {
    __nv_bfloat16 ha = __float2bfloat16_rn(a);
    __nv_bfloat16 hb = __float2bfloat16_rn(b);
    float ra = a - __bfloat162float(ha);
    float rb = b - __bfloat162float(hb);
    __nv_bfloat16 la = __float2bfloat16_rn(ra);
    __nv_bfloat16 lb = __float2bfloat16_rn(rb);
    hi = ((uint32_t)__bfloat16_as_ushort(hb) << 16) | (uint32_t)__bfloat16_as_ushort(ha);
    lo = ((uint32_t)__bfloat16_as_ushort(lb) << 16) | (uint32_t)__bfloat16_as_ushort(la);
}

__device__ __forceinline__ void mma_bf16(float* c, const uint32_t* a,
                                         uint32_t b0, uint32_t b1) {
    asm volatile(
        "mma.sync.aligned.m16n8k16.row.col.f32.bf16.bf16.f32 "
        "{%0,%1,%2,%3}, {%4,%5,%6,%7}, {%8,%9}, {%0,%1,%2,%3};"
        : "+f"(c[0]), "+f"(c[1]), "+f"(c[2]), "+f"(c[3])
        : "r"(a[0]), "r"(a[1]), "r"(a[2]), "r"(a[3]), "r"(b0), "r"(b1));
}

// ---------------- setup kernels ----------------
// W_self[l][k][n], W_neigh[l][k][n] -> pre-split bf16 planes [l][n][kpair]
__global__ void wt_kernel(const float* __restrict__ Wself,
                          const float* __restrict__ Wneigh) {
    int idx = blockIdx.x * blockDim.x + threadIdx.x;   // 2*128*128 = 32768 kpairs
    if (idx >= 2 * 128 * 128) return;
    int l = idx >> 14;
    int rem = idx & 16383;
    int n = rem >> 7;
    int kp = rem & 127;
    float w0, w1;
    if (kp < 64) {
        int k = 2 * kp;
        w0 = Wself[l * 16384 + k * 128 + n];
        w1 = Wself[l * 16384 + (k + 1) * 128 + n];
    } else {
        int k = 2 * kp - 128;
        w0 = Wneigh[l * 16384 + k * 128 + n];
        w1 = Wneigh[l * 16384 + (k + 1) * 128 + n];
    }
    uint32_t hi, lo;
    split2(w0, w1, hi, lo);
    g_WThi[idx] = hi;
    g_WTlo[idx] = lo;
}

// 4 edges per thread via int4
__global__ void degree_kernel(const int* __restrict__ edst, int E) {
    int e4 = blockIdx.x * blockDim.x + threadIdx.x;
    int n4 = E >> 2;
    if (e4 < n4) {
        int4 v = ((const int4*)edst)[e4];
        atomicAdd(&g_deg[v.x], 1);
        atomicAdd(&g_deg[v.y], 1);
        atomicAdd(&g_deg[v.z], 1);
        atomicAdd(&g_deg[v.w], 1);
    }
    if (e4 == 0) {
        for (int e = n4 * 4; e < E; e++) atomicAdd(&g_deg[edst[e]], 1);
    }
}

// fast single-CTA scan: 10 elems/thread + warp/block shuffle scan
__global__ void __launch_bounds__(1024) scan_kernel(int E) {
    __shared__ int wsum[32];
    int tid = threadIdx.x;
    int lane = tid & 31;
    int w = tid >> 5;
    int base = tid * 10;
    int d[10];
    int tot = 0;
#pragma unroll
    for (int j = 0; j < 10; j++) {
        int idx = base + j;
        d[j] = (idx < NNODES) ? g_deg[idx] : 0;
        tot += d[j];
    }
    int inc = tot;
#pragma unroll
    for (int off = 1; off < 32; off <<= 1) {
        int nv = __shfl_up_sync(0xffffffffu, inc, off);
        if (lane >= off) inc += nv;
    }
    if (lane == 31) wsum[w] = inc;
    __syncthreads();
    if (w == 0) {
        int v = wsum[lane];
        int i2 = v;
#pragma unroll
        for (int off = 1; off < 32; off <<= 1) {
            int nv = __shfl_up_sync(0xffffffffu, i2, off);
            if (lane >= off) i2 += nv;
        }
        wsum[lane] = i2 - v;   // exclusive warp offsets
    }
    __syncthreads();
    int run = wsum[w] + inc - tot;
#pragma unroll
    for (int j = 0; j < 10; j++) {
        int idx = base + j;
        if (idx < NNODES) {
            g_off[idx] = run;
            g_invdeg[idx] = (d[j] > 0) ? (1.0f / (float)d[j]) : 0.0f;
        }
        run += d[j];
    }
    if (tid == 0) g_off[NNODES] = E;
}

__global__ void bucket_kernel(const int* __restrict__ esrc,
                              const int* __restrict__ edst, int E) {
    int e4 = blockIdx.x * blockDim.x + threadIdx.x;
    int n4 = E >> 2;
    if (e4 < n4) {
        int4 s = ((const int4*)esrc)[e4];
        int4 d = ((const int4*)edst)[e4];
        int p;
        p = g_off[d.x] + atomicAdd(&g_cursor[d.x], 1); g_esrc_sorted[p] = s.x;
        p = g_off[d.y] + atomicAdd(&g_cursor[d.y], 1); g_esrc_sorted[p] = s.y;
        p = g_off[d.z] + atomicAdd(&g_cursor[d.z], 1); g_esrc_sorted[p] = s.z;
        p = g_off[d.w] + atomicAdd(&g_cursor[d.w], 1); g_esrc_sorted[p] = s.w;
    }
    if (e4 == 0) {
        for (int e = n4 * 4; e < E; e++) {
            int dn = edst[e];
            int p = g_off[dn] + atomicAdd(&g_cursor[dn], 1);
            g_esrc_sorted[p] = esrc[e];
        }
    }
}

// ---------------- mean aggregation: one CTA per dst node ----------------
// layer 0 reads feat [bt][n][f] directly; layer 1 reads g_hB [n][bt][f].
// Output g_agg is node-major [n][bt][f].
__global__ void __launch_bounds__(128) agg_kernel(const float* __restrict__ feat,
                                                  int src_sel) {
    int n = blockIdx.x;
    int t = threadIdx.x;
    int s = g_off[n];
    int e = g_off[n + 1];
    float4 a0 = make_float4(0.f, 0.f, 0.f, 0.f);
    float4 a1 = make_float4(0.f, 0.f, 0.f, 0.f);
    float4 a2 = make_float4(0.f, 0.f, 0.f, 0.f);
    float4 a3 = make_float4(0.f, 0.f, 0.f, 0.f);
    int i = s;
    if (src_sel == 0) {
        const float4* hv = (const float4*)feat;
        int bt = t >> 5;                 // 0..3
        int f4 = t & 31;                 // 0..31
        int boff = bt * NNODES * 32 + f4;
        for (; i + 3 < e; i += 4) {
            int s0 = g_esrc_sorted[i];
            int s1 = g_esrc_sorted[i + 1];
            int s2 = g_esrc_sorted[i + 2];
            int s3 = g_esrc_sorted[i + 3];
            float4 v0 = hv[boff + s0 * 32];
            float4 v1 = hv[boff + s1 * 32];
            float4 v2 = hv[boff + s2 * 32];
            float4 v3 = hv[boff + s3 * 32];
            a0.x += v0.x; a0.y += v0.y; a0.z += v0.z; a0.w += v0.w;
            a1.x += v1.x; a1.y += v1.y; a1.z += v1.z; a1.w += v1.w;
            a2.x += v2.x; a2.y += v2.y; a2.z += v2.z; a2.w += v2.w;
            a3.x += v3.x; a3.y += v3.y; a3.z += v3.z; a3.w += v3.w;
        }
        for (; i < e; i++) {
            int s0 = g_esrc_sorted[i];
            float4 v0 = hv[boff + s0 * 32];
            a0.x += v0.x; a0.y += v0.y; a0.z += v0.z; a0.w += v0.w;
        }
    } else {
        const float4* hv = (const float4*)g_hB;
        for (; i + 3 < e; i += 4) {
            int s0 = g_esrc_sorted[i];
            int s1 = g_esrc_sorted[i + 1];
            int s2 = g_esrc_sorted[i + 2];
            int s3 = g_esrc_sorted[i + 3];
            float4 v0 = hv[s0 * 128 + t];
            float4 v1 = hv[s1 * 128 + t];
            float4 v2 = hv[s2 * 128 + t];
            float4 v3 = hv[s3 * 128 + t];
            a0.x += v0.x; a0.y += v0.y; a0.z += v0.z; a0.w += v0.w;
            a1.x += v1.x; a1.y += v1.y; a1.z += v1.z; a1.w += v1.w;
            a2.x += v2.x; a2.y += v2.y; a2.z += v2.z; a2.w += v2.w;
            a3.x += v3.x; a3.y += v3.y; a3.z += v3.z; a3.w += v3.w;
        }
        for (; i < e; i++) {
            int s0 = g_esrc_sorted[i];
            float4 v0 = hv[s0 * 128 + t];
            a0.x += v0.x; a0.y += v0.y; a0.z += v0.z; a0.w += v0.w;
        }
    }
    float inv = g_invdeg[n];
    float4 r;
    r.x = (a0.x + a1.x + a2.x + a3.x) * inv;
    r.y = (a0.y + a1.y + a2.y + a3.y) * inv;
    r.z = (a0.z + a1.z + a2.z + a3.z) * inv;
    r.w = (a0.w + a1.w + a2.w + a3.w) * inv;
    ((float4*)g_agg)[n * 128 + t] = r;
}

// ---------------- persistent mma.sync bf16x2-split GEMM ----------------
// out[m][n] = sum_k X[m][k]*W[k][n] + b[n]; M=40000, K=256, N=128.
// B pre-split planes staged to smem ONCE per CTA; tiles claimed via atomic.
// layer 0: X0 = feat ([bt][n][f] indexing); layer 1: X0 = g_hB (node-major).
__global__ void __launch_bounds__(256) gemm_mma(const float* __restrict__ feat,
                                                int layer,
                                                const float* __restrict__ bias,
                                                float* __restrict__ out_ext) {
    extern __shared__ uint32_t sm[];
    __shared__ int s_tile;
    uint32_t* Bhi = sm + B_HI_OFF;
    uint32_t* Blo = sm + B_LO_OFF;
    float* sbias = (float*)(sm + BIAS_OFF);

    int tid = threadIdx.x;
    int lane = tid & 31;
    int warp = tid >> 5;
    int g = lane >> 2;
    int t = lane & 3;
    int wr = (warp & 3) * 32;
    int wc = (warp >> 2) * 64;

    if (tid < 128) sbias[tid] = bias[tid];

    // stage B once: straight uint4 copy of pre-split planes
    const uint4* bhv = (const uint4*)(g_WThi + layer * 128 * 128);
    const uint4* blv = (const uint4*)(g_WTlo + layer * 128 * 128);
#pragma unroll
    for (int i = 0; i < 16; i++) {
        int lin = tid + i * 256;
        int n = lin >> 5;
        int j = lin & 31;
        *(uint4*)&Bhi[n * BKS + 4 * j] = bhv[lin];
        *(uint4*)&Blo[n * BKS + 4 * j] = blv[lin];
    }

    const float4* x0v = (layer == 0) ? (const float4*)feat : (const float4*)g_hB;
    const float4* x1v = (const float4*)g_agg;

    while (true) {
        if (tid == 0) s_tile = atomicAdd(&g_tilectr[layer], 1);
        __syncthreads();
        int tnum = s_tile;
        if (tnum >= NTILES) break;
        int tile = tnum * 128;

        float acc[2][8][4];
#pragma unroll
        for (int rb = 0; rb < 2; rb++)
#pragma unroll
            for (int nb = 0; nb < 8; nb++)
#pragma unroll
                for (int c = 0; c < 4; c++) acc[rb][nb][c] = 0.f;

        // preload chunk 0 (8 float4 per thread)
        float4 v[8];
#pragma unroll
        for (int i = 0; i < 8; i++) {
            int lin = tid + i * 256;
            int row = lin >> 4;
            int j = lin & 15;
            int m = tile + row;
            if (m >= MROWS) m = MROWS - 1;
            if (layer == 0) {
                // j4 = j < 32 always for kc=0: X0 path
                int node = m >> 2;
                int bt = m & 3;
                v[i] = x0v[(bt * NNODES + node) * 32 + j];
            } else {
                v[i] = x0v[m * 32 + j];
            }
        }

        for (int kc = 0; kc < 4; kc++) {
            uint32_t* Ahi = sm + A_HI_OFF + (kc & 1) * ABUF;
            uint32_t* Alo = sm + A_LO_OFF + (kc & 1) * ABUF;
#pragma unroll
            for (int i = 0; i < 8; i++) {
                int lin = tid + i * 256;
                int row = lin >> 4;
                int j = lin & 15;
                uint32_t h0, l0, h1, l1;
                split2(v[i].x, v[i].y, h0, l0);
                split2(v[i].z, v[i].w, h1, l1);
                *(uint2*)&Ahi[row * AKS + 2 * j] = make_uint2(h0, h1);
                *(uint2*)&Alo[row * AKS + 2 * j] = make_uint2(l0, l1);
            }
            __syncthreads();

            if (kc < 3) {
#pragma unroll
                for (int i = 0; i < 8; i++) {
                    int lin = tid + i * 256;
                    int row = lin >> 4;
                    int j = lin & 15;
                    int m = tile + row;
                    if (m >= MROWS) m = MROWS - 1;
                    int j4 = (kc + 1) * 16 + j;
                    if (j4 < 32) {
                        if (layer == 0) {
                            int node = m >> 2;
                            int bt = m & 3;
                            v[i] = x0v[(bt * NNODES + node) * 32 + j4];
                        } else {
                            v[i] = x0v[m * 32 + j4];
                        }
                    } else {
                        v[i] = x1v[m * 32 + (j4 - 32)];
                    }
                }
            }

#pragma unroll
            for (int ks = 0; ks < 4; ks++) {
                int kb = ks * 8;
                int gb = kc * 32 + kb;
                uint32_t ah[2][4], al[2][4];
#pragma unroll
                for (int rb = 0; rb < 2; rb++) {
                    int r0 = (wr + rb * 16 + g) * AKS;
                    int r1 = r0 + 8 * AKS;
                    ah[rb][0] = Ahi[r0 + kb + t];
                    ah[rb][1] = Ahi[r1 + kb + t];
                    ah[rb][2] = Ahi[r0 + kb + t + 4];
                    ah[rb][3] = Ahi[r1 + kb + t + 4];
                    al[rb][0] = Alo[r0 + kb + t];
                    al[rb][1] = Alo[r1 + kb + t];
                    al[rb][2] = Alo[r0 + kb + t + 4];
                    al[rb][3] = Alo[r1 + kb + t + 4];
                }
#pragma unroll
                for (int nb = 0; nb < 8; nb++) {
                    int boff = (wc + nb * 8 + g) * BKS + gb;
                    uint32_t bh0 = Bhi[boff + t];
                    uint32_t bh1 = Bhi[boff + t + 4];
                    uint32_t bl0 = Blo[boff + t];
                    uint32_t bl1 = Blo[boff + t + 4];
#pragma unroll
                    for (int rb = 0; rb < 2; rb++) {
                        mma_bf16(acc[rb][nb], ah[rb], bh0, bh1);
                        mma_bf16(acc[rb][nb], ah[rb], bl0, bl1);
                        mma_bf16(acc[rb][nb], al[rb], bh0, bh1);
                    }
                }
            }
        }

        // epilogue
#pragma unroll
        for (int rb = 0; rb < 2; rb++) {
#pragma unroll
            for (int h = 0; h < 2; h++) {
                int m = tile + wr + rb * 16 + g + h * 8;
                if (m < MROWS) {
                    float* op;
                    if (layer == 0) {
                        op = g_hB + (size_t)m * 128;
                    } else {
                        int n = m >> 2;
                        int bt = m & 3;
                        op = out_ext + ((size_t)bt * NNODES + n) * 128;
                    }
#pragma unroll
                    for (int nb = 0; nb < 8; nb++) {
                        int col = wc + nb * 8 + 2 * t;
                        float2 vv;
                        vv.x = acc[rb][nb][h * 2 + 0] + sbias[col];
                        vv.y = acc[rb][nb][h * 2 + 1] + sbias[col + 1];
                        *(float2*)(op + col) = vv;
                    }
                }
            }
        }
        __syncthreads();   // protect s_tile / A buffers before next claim
    }
}

// ---------------- launch ----------------
extern "C" void kernel_launch(void* const* d_in, const int* in_sizes, int n_in,
                              void* d_out, int out_size) {
    const float* feat   = (const float*)d_in[0];
    const float* Wself  = (const float*)d_in[1];
    const float* Wneigh = (const float*)d_in[2];
    const float* bias   = (const float*)d_in[3];
    const int*   esrc   = (const int*)d_in[4];
    const int*   edst   = (const int*)d_in[5];
    int E = in_sizes[4];

    cudaFuncSetAttribute(gemm_mma, cudaFuncAttributeMaxDynamicSharedMemorySize,
                         GSMEM_BYTES);

    void *p_deg, *p_cur, *p_ctr;
    cudaGetSymbolAddress(&p_deg, g_deg);
    cudaGetSymbolAddress(&p_cur, g_cursor);
    cudaGetSymbolAddress(&p_ctr, g_tilectr);
    cudaMemsetAsync(p_deg, 0, NNODES * sizeof(int));
    cudaMemsetAsync(p_cur, 0, NNODES * sizeof(int));
    cudaMemsetAsync(p_ctr, 0, 2 * sizeof(int));

    wt_kernel<<<(2 * 128 * 128 + 255) / 256, 256>>>(Wself, Wneigh);
    degree_kernel<<<((E / 4) + 255) / 256, 256>>>(edst, E);
    scan_kernel<<<1, 1024>>>(E);
    bucket_kernel<<<((E / 4) + 255) / 256, 256>>>(esrc, edst, E);

    // layer 0: agg(feat) -> g_agg, gemm(feat, agg) -> g_hB
    agg_kernel<<<NNODES, 128>>>(feat, 0);
    gemm_mma<<<152, 256, GSMEM_BYTES>>>(feat, 0, bias, (float*)d_out);

    // layer 1: agg(g_hB) -> g_agg, gemm(g_hB, agg) -> d_out ([B,T,N,F])
    agg_kernel<<<NNODES, 128>>>(feat, 1);
    gemm_mma<<<152, 256, GSMEM_BYTES>>>(feat, 1, bias + 128, (float*)d_out);
}